// round 11
// baseline (speedup 1.0000x reference)
#include <cuda_runtime.h>
#define TPB 256
#define MAXBLK 4608

__device__ double g_po[MAXBLK], g_pm[MAXBLK];
__device__ unsigned int g_cnt = 0;

// netlib slarfg fp32 (UNCHANGED — load-bearing for correctness)
__device__ __forceinline__ float larfg(float al,float xn,float& tau,float& rs){
    tau=0.f; rs=0.f;
    if(xn!=0.f){
        float ax=fabsf(al),ay=fabsf(xn),w=fmaxf(ax,ay),z=fminf(ax,ay);
        float p=(z==0.f)?w:__fmul_rn(w,__fsqrt_rn(__fmaf_rn(__fdiv_rn(z,w),__fdiv_rn(z,w),1.f)));
        float be=-copysignf(p,al);
        tau=__fdiv_rn(__fsub_rn(be,al),be);
        rs=__fdiv_rn(1.f,__fsub_rn(al,be));
        return be;
    }
    return al;
}

__device__ __forceinline__ void top2(float a00,float a11,float a22,float a01,float a02,float a12,float& s1,float& s2){
    float q=(a00+a11+a22)*(1.f/3.f);
    float b00=a00-q,b11=a11-q,b22=a22-q;
    float p2=fmaf(b00,b00,fmaf(b11,b11,b22*b22))+2.f*fmaf(a01,a01,fmaf(a02,a02,a12*a12));
    float p=sqrtf(p2*(1.f/6.f));
    float pi=(p>0.f)?(1.f/p):0.f;
    float c00=b00*pi,c11=b11*pi,c22=b22*pi,c01=a01*pi,c02=a02*pi,c12=a12*pi;
    float dB=c00*fmaf(c11,c22,-c12*c12)-c01*fmaf(c01,c22,-c12*c02)+c02*fmaf(c01,c12,-c11*c02);
    float r=fminf(fmaxf(.5f*dB,-1.f),1.f);
    float phi=acosf(r)*(1.f/3.f);
    float l1=q+2.f*p*cosf(phi);
    float l3=q+2.f*p*cosf(phi+2.0943951023931953f);
    float l2=3.f*q-l1-l3;
    s1=sqrtf(fmaxf(l1,1e-30f)); s2=sqrtf(fmaxf(l2,1e-30f));
}

// fp32 sgebd2 (bit-exact netlib orderings) + all-fp32 bidiagonal SVD (UNCHANGED from R9)
__device__ __noinline__ void sv_lapack(
    float a00,float a10,float a20, float a01,float a11,float a21,
    float a02,float a12,float a22, float& S1,float& S2,float& S3)
{
    float tau,rs;
    float xn=(float)sqrt((double)a10*(double)a10+(double)a20*(double)a20);
    float d1=larfg(a00,xn,tau,rs);
    float v2=__fmul_rn(a10,rs), v3=__fmul_rn(a20,rs);
    float wA=__fmaf_rn(a21,v3,__fmaf_rn(a11,v2,a01));
    float wB=__fmaf_rn(a22,v3,__fmaf_rn(a12,v2,a02));
    float tA=__fmul_rn(-tau,wA), tB=__fmul_rn(-tau,wB);
    a01=__fadd_rn(a01,tA); a11=__fmaf_rn(v2,tA,a11); a21=__fmaf_rn(v3,tA,a21);
    a02=__fadd_rn(a02,tB); a12=__fmaf_rn(v2,tB,a12); a22=__fmaf_rn(v3,tB,a22);
    float e1=larfg(a01,fabsf(a02),tau,rs);
    float r2=__fmul_rn(a02,rs);
    wA=__fmaf_rn(a12,r2,a11);
    wB=__fmaf_rn(a22,r2,a21);
    float t1=-tau;
    float t2=__fmul_rn(-tau,r2);
    a11=__fmaf_rn(wA,t1,a11); a21=__fmaf_rn(wB,t1,a21);
    a12=__fmaf_rn(wA,t2,a12); a22=__fmaf_rn(wB,t2,a22);
    float d2=larfg(a11,fabsf(a21),tau,rs);
    float u2=__fmul_rn(a21,rs);
    float w=__fmaf_rn(a22,u2,a12);
    float tt=__fmul_rn(-tau,w);
    a12=__fadd_rn(a12,tt); a22=__fmaf_rn(u2,tt,a22);
    float e2=a12, d3=a22;

    float g00=d1*d1, g01=d1*e1, g11=fmaf(e1,e1,d2*d2), g12=d2*e2, g22=fmaf(e2,e2,d3*d3);
    float s1,s2; top2(g00,g11,g22,g01,0.f,g12,s1,s2);
    float det=fabsf(__fmul_rn(__fmul_rn(d1,d2),d3));
    S1=s1; S2=s2;
    S3=__fdiv_rn(det,__fmul_rn(s1,s2));
}

__global__ void __launch_bounds__(TPB)
tl_fused(const float4* __restrict__ th, const float4* __restrict__ af,
         float* __restrict__ out, int n, int nblk)
{
    int tid=threadIdx.x;
    int i=blockIdx.x*TPB+tid;
    float oA=0.f, mA=0.f;

    if(i<n){
        float4 t0=__ldcs(&th[3*i+0]), t1=__ldcs(&th[3*i+1]), t2=__ldcs(&th[3*i+2]);
        float4 a0=__ldcs(&af[3*i+0]), a1=__ldcs(&af[3*i+1]), a2=__ldcs(&af[3*i+2]);

        float d,m=0.f;
        d=t0.x-a0.x; m=fmaf(d,d,m); d=t0.y-a0.y; m=fmaf(d,d,m);
        d=t0.z-a0.z; m=fmaf(d,d,m); d=t0.w-a0.w; m=fmaf(d,d,m);
        d=t1.x-a1.x; m=fmaf(d,d,m); d=t1.y-a1.y; m=fmaf(d,d,m);
        d=t1.z-a1.z; m=fmaf(d,d,m); d=t1.w-a1.w; m=fmaf(d,d,m);
        d=t2.x-a2.x; m=fmaf(d,d,m); d=t2.y-a2.y; m=fmaf(d,d,m);
        d=t2.z-a2.z; m=fmaf(d,d,m); d=t2.w-a2.w; m=fmaf(d,d,m);
        mA = m;

        float w0=t0.x,w1=t0.y,w2=t0.z, w3=t1.x,w4=t1.y,w5=t1.z, w6=t2.x,w7=t2.y,w8=t2.z;
        float a00=fmaf(w0,w0,fmaf(w3,w3,w6*w6));
        float a11=fmaf(w1,w1,fmaf(w4,w4,w7*w7));
        float a22=fmaf(w2,w2,fmaf(w5,w5,w8*w8));
        float a01=fmaf(w0,w1,fmaf(w3,w4,w6*w7));
        float a02=fmaf(w0,w2,fmaf(w3,w5,w6*w8));
        float a12=fmaf(w1,w2,fmaf(w4,w5,w7*w8));
        float tr = a00+a11+a22;
        float tradj = fmaf(a11,a22,-a12*a12)
                    + fmaf(a00,a22,-a02*a02)
                    + fmaf(a00,a11,-a01*a01);
        float c0=fmaf(w4,w8,-w5*w7), c1=fmaf(w3,w8,-w5*w6), c2=fmaf(w3,w7,-w4*w6);
        float det=fmaf(w2,c2,fmaf(-w1,c1,w0*c0));
        float d2=det*det;

        if (d2 < 4e-6f*tradj) {
            float s1,s2,s3;
            sv_lapack(w0,w3,w6, w1,w4,w7, w2,w5,w8, s1,s2,s3);
            float u1=__fadd_rn(s1,1e-6f), u2=__fadd_rn(s2,1e-6f), u3=__fadd_rn(s3,1e-6f);
            float q1=__fmul_rn(u1,u1), q2=__fmul_rn(u2,u2), q3=__fmul_rn(u3,u3);
            float v1=__fadd_rn(q1,__fdiv_rn(1.f,q1));
            float v2=__fadd_rn(q2,__fdiv_rn(1.f,q2));
            float v3=__fadd_rn(q3,__fdiv_rn(1.f,q3));
            oA=__fadd_rn(__fadd_rn(v1,v2),v3);
        } else {
            oA = tr + __fdividef(tradj, d2);
        }
    }

    __shared__ double so[TPB], sm[TPB];
    so[tid]=(double)oA;
    sm[tid]=(double)mA;
    __syncthreads();
    #pragma unroll
    for(int s=TPB/2;s>0;s>>=1){
        if(tid<s){ so[tid]+=so[tid+s]; sm[tid]+=sm[tid+s]; }
        __syncthreads();
    }
    __shared__ bool isLast;
    if(tid==0){
        g_po[blockIdx.x]=so[0];
        g_pm[blockIdx.x]=sm[0];
        __threadfence();
        unsigned v=atomicAdd(&g_cnt,1u);
        isLast=(v==(unsigned)(nblk-1));
    }
    __syncthreads();

    if(isLast){
        double o=0.0,mm=0.0;
        for(int j=tid;j<nblk;j+=TPB){ o+=g_po[j]; mm+=g_pm[j]; }
        so[tid]=o; sm[tid]=mm;
        __syncthreads();
        #pragma unroll
        for(int s=TPB/2;s>0;s>>=1){
            if(tid<s){ so[tid]+=so[tid+s]; sm[tid]+=sm[tid+s]; }
            __syncthreads();
        }
        if(tid==0){
            double B=(double)n;
            out[0]=(float)(so[0]/B-6.0);
            out[1]=(float)(sm[0]/(B*12.0));
            g_cnt=0;
        }
    }
}

extern "C" void kernel_launch(void* const* d_in, const int* in_sizes, int n_in,
                              void* d_out, int out_size)
{
    const float4* th=(const float4*)d_in[0];
    const float4* af=(const float4*)d_in[1];
    int n=in_sizes[0]/12;
    int nblk=(n+TPB-1)/TPB;
    if(nblk>MAXBLK) nblk=MAXBLK;   // n=1M -> 4096 blocks, fits
    if(nblk<1) nblk=1;
    tl_fused<<<nblk,TPB>>>(th,af,(float*)d_out,n,nblk);
}

// round 12
// speedup vs baseline: 1.8776x; 1.8776x over previous
#include <cuda_runtime.h>
#define TPB 256
#define NBLK 1184
#define MAXBLK 2048

__device__ double g_po[MAXBLK], g_pm[MAXBLK];
__device__ unsigned int g_cnt = 0;

// netlib slarfg fp32 (UNCHANGED — load-bearing for correctness)
__device__ __forceinline__ float larfg(float al,float xn,float& tau,float& rs){
    tau=0.f; rs=0.f;
    if(xn!=0.f){
        float ax=fabsf(al),ay=fabsf(xn),w=fmaxf(ax,ay),z=fminf(ax,ay);
        float p=(z==0.f)?w:__fmul_rn(w,__fsqrt_rn(__fmaf_rn(__fdiv_rn(z,w),__fdiv_rn(z,w),1.f)));
        float be=-copysignf(p,al);
        tau=__fdiv_rn(__fsub_rn(be,al),be);
        rs=__fdiv_rn(1.f,__fsub_rn(al,be));
        return be;
    }
    return al;
}

__device__ __forceinline__ void top2(float a00,float a11,float a22,float a01,float a02,float a12,float& s1,float& s2){
    float q=(a00+a11+a22)*(1.f/3.f);
    float b00=a00-q,b11=a11-q,b22=a22-q;
    float p2=fmaf(b00,b00,fmaf(b11,b11,b22*b22))+2.f*fmaf(a01,a01,fmaf(a02,a02,a12*a12));
    float p=sqrtf(p2*(1.f/6.f));
    float pi=(p>0.f)?(1.f/p):0.f;
    float c00=b00*pi,c11=b11*pi,c22=b22*pi,c01=a01*pi,c02=a02*pi,c12=a12*pi;
    float dB=c00*fmaf(c11,c22,-c12*c12)-c01*fmaf(c01,c22,-c12*c02)+c02*fmaf(c01,c12,-c11*c02);
    float r=fminf(fmaxf(.5f*dB,-1.f),1.f);
    float phi=acosf(r)*(1.f/3.f);
    float l1=q+2.f*p*cosf(phi);
    float l3=q+2.f*p*cosf(phi+2.0943951023931953f);
    float l2=3.f*q-l1-l3;
    s1=sqrtf(fmaxf(l1,1e-30f)); s2=sqrtf(fmaxf(l2,1e-30f));
}

// fp32 sgebd2 (bit-exact netlib orderings) + all-fp32 bidiagonal SVD (UNCHANGED from R9)
__device__ __noinline__ void sv_lapack(
    float a00,float a10,float a20, float a01,float a11,float a21,
    float a02,float a12,float a22, float& S1,float& S2,float& S3)
{
    float tau,rs;
    float xn=(float)sqrt((double)a10*(double)a10+(double)a20*(double)a20);
    float d1=larfg(a00,xn,tau,rs);
    float v2=__fmul_rn(a10,rs), v3=__fmul_rn(a20,rs);
    float wA=__fmaf_rn(a21,v3,__fmaf_rn(a11,v2,a01));
    float wB=__fmaf_rn(a22,v3,__fmaf_rn(a12,v2,a02));
    float tA=__fmul_rn(-tau,wA), tB=__fmul_rn(-tau,wB);
    a01=__fadd_rn(a01,tA); a11=__fmaf_rn(v2,tA,a11); a21=__fmaf_rn(v3,tA,a21);
    a02=__fadd_rn(a02,tB); a12=__fmaf_rn(v2,tB,a12); a22=__fmaf_rn(v3,tB,a22);
    float e1=larfg(a01,fabsf(a02),tau,rs);
    float r2=__fmul_rn(a02,rs);
    wA=__fmaf_rn(a12,r2,a11);
    wB=__fmaf_rn(a22,r2,a21);
    float t1=-tau;
    float t2=__fmul_rn(-tau,r2);
    a11=__fmaf_rn(wA,t1,a11); a21=__fmaf_rn(wB,t1,a21);
    a12=__fmaf_rn(wA,t2,a12); a22=__fmaf_rn(wB,t2,a22);
    float d2=larfg(a11,fabsf(a21),tau,rs);
    float u2=__fmul_rn(a21,rs);
    float w=__fmaf_rn(a22,u2,a12);
    float tt=__fmul_rn(-tau,w);
    a12=__fadd_rn(a12,tt); a22=__fmaf_rn(u2,tt,a22);
    float e2=a12, d3=a22;

    float g00=d1*d1, g01=d1*e1, g11=fmaf(e1,e1,d2*d2), g12=d2*e2, g22=fmaf(e2,e2,d3*d3);
    float s1,s2; top2(g00,g11,g22,g01,0.f,g12,s1,s2);
    float det=fabsf(__fmul_rn(__fmul_rn(d1,d2),d3));
    S1=s1; S2=s2;
    S3=__fdiv_rn(det,__fmul_rn(s1,s2));
}

__global__ void __launch_bounds__(TPB, 8)   // cap regs at 32 -> 8 CTAs/SM
tl_fused(const float4* __restrict__ th, const float4* __restrict__ af,
         float* __restrict__ out, int n, int nblk)
{
    int tid=threadIdx.x;
    int stride=nblk*TPB;
    float oA=0.f, mA=0.f;

    for(int i=blockIdx.x*TPB+tid; i<n; i+=stride){
        float4 t0=__ldcs(&th[3*i+0]), t1=__ldcs(&th[3*i+1]), t2=__ldcs(&th[3*i+2]);
        float4 a0=__ldcs(&af[3*i+0]), a1=__ldcs(&af[3*i+1]), a2=__ldcs(&af[3*i+2]);

        float d,m=0.f;
        d=t0.x-a0.x; m=fmaf(d,d,m); d=t0.y-a0.y; m=fmaf(d,d,m);
        d=t0.z-a0.z; m=fmaf(d,d,m); d=t0.w-a0.w; m=fmaf(d,d,m);
        d=t1.x-a1.x; m=fmaf(d,d,m); d=t1.y-a1.y; m=fmaf(d,d,m);
        d=t1.z-a1.z; m=fmaf(d,d,m); d=t1.w-a1.w; m=fmaf(d,d,m);
        d=t2.x-a2.x; m=fmaf(d,d,m); d=t2.y-a2.y; m=fmaf(d,d,m);
        d=t2.z-a2.z; m=fmaf(d,d,m); d=t2.w-a2.w; m=fmaf(d,d,m);
        mA += m;

        float w0=t0.x,w1=t0.y,w2=t0.z, w3=t1.x,w4=t1.y,w5=t1.z, w6=t2.x,w7=t2.y,w8=t2.z;
        float a00=fmaf(w0,w0,fmaf(w3,w3,w6*w6));
        float a11=fmaf(w1,w1,fmaf(w4,w4,w7*w7));
        float a22=fmaf(w2,w2,fmaf(w5,w5,w8*w8));
        float a01=fmaf(w0,w1,fmaf(w3,w4,w6*w7));
        float a02=fmaf(w0,w2,fmaf(w3,w5,w6*w8));
        float a12=fmaf(w1,w2,fmaf(w4,w5,w7*w8));
        float tr = a00+a11+a22;
        float tradj = fmaf(a11,a22,-a12*a12)
                    + fmaf(a00,a22,-a02*a02)
                    + fmaf(a00,a11,-a01*a01);
        float c0=fmaf(w4,w8,-w5*w7), c1=fmaf(w3,w8,-w5*w6), c2=fmaf(w3,w7,-w4*w6);
        float det=fmaf(w2,c2,fmaf(-w1,c1,w0*c0));
        float d2=det*det;

        float term;
        if (d2 < 4e-6f*tradj) {
            float s1,s2,s3;
            sv_lapack(w0,w3,w6, w1,w4,w7, w2,w5,w8, s1,s2,s3);
            float u1=__fadd_rn(s1,1e-6f), u2=__fadd_rn(s2,1e-6f), u3=__fadd_rn(s3,1e-6f);
            float q1=__fmul_rn(u1,u1), q2=__fmul_rn(u2,u2), q3=__fmul_rn(u3,u3);
            float v1=__fadd_rn(q1,__fdiv_rn(1.f,q1));
            float v2=__fadd_rn(q2,__fdiv_rn(1.f,q2));
            float v3=__fadd_rn(q3,__fdiv_rn(1.f,q3));
            term=__fadd_rn(__fadd_rn(v1,v2),v3);
        } else {
            term = tr + __fdividef(tradj, d2);
        }
        oA += term;
    }

    __shared__ double so[TPB], sm[TPB];
    so[tid]=(double)oA;
    sm[tid]=(double)mA;
    __syncthreads();
    #pragma unroll
    for(int s=TPB/2;s>0;s>>=1){
        if(tid<s){ so[tid]+=so[tid+s]; sm[tid]+=sm[tid+s]; }
        __syncthreads();
    }
    __shared__ bool isLast;
    if(tid==0){
        g_po[blockIdx.x]=so[0];
        g_pm[blockIdx.x]=sm[0];
        __threadfence();
        unsigned v=atomicAdd(&g_cnt,1u);
        isLast=(v==(unsigned)(nblk-1));
    }
    __syncthreads();

    if(isLast){
        double o=0.0,mm=0.0;
        for(int j=tid;j<nblk;j+=TPB){ o+=g_po[j]; mm+=g_pm[j]; }
        so[tid]=o; sm[tid]=mm;
        __syncthreads();
        #pragma unroll
        for(int s=TPB/2;s>0;s>>=1){
            if(tid<s){ so[tid]+=so[tid+s]; sm[tid]+=sm[tid+s]; }
            __syncthreads();
        }
        if(tid==0){
            double B=(double)n;
            out[0]=(float)(so[0]/B-6.0);
            out[1]=(float)(sm[0]/(B*12.0));
            g_cnt=0;
        }
    }
}

extern "C" void kernel_launch(void* const* d_in, const int* in_sizes, int n_in,
                              void* d_out, int out_size)
{
    const float4* th=(const float4*)d_in[0];
    const float4* af=(const float4*)d_in[1];
    int n=in_sizes[0]/12;
    int nblk=NBLK;
    int maxb=(n+TPB-1)/TPB;
    if(nblk>maxb) nblk=maxb;
    if(nblk<1) nblk=1;
    tl_fused<<<nblk,TPB>>>(th,af,(float*)d_out,n,nblk);
}